// round 3
// baseline (speedup 1.0000x reference)
#include <cuda_runtime.h>
#include <math.h>

// Problem constants
#define Bb 4
#define Ss 20
#define IMm 64
#define Dd 8
#define NLl 4
#define NPOS (Bb*Ss*IMm*IMm)
#define NELEM (NPOS*Dd)
#define LOG2E 1.4426950408889634f

// Scratch (no allocations allowed)
__device__ float g_xt[NELEM];
__device__ float g_bufA[NELEM];
__device__ float g_bufB[NELEM];
__device__ float g_logits[Bb];

// ---------------- packed f32x2 helpers (sm_103a) ----------------
typedef unsigned long long u64t;
__device__ __forceinline__ u64t pk2(float lo, float hi) {
    u64t r; asm("mov.b64 %0, {%1,%2};" : "=l"(r) : "f"(lo), "f"(hi)); return r;
}
__device__ __forceinline__ void up2(u64t v, float& a, float& b) {
    asm("mov.b64 {%0,%1}, %2;" : "=f"(a), "=f"(b) : "l"(v));
}
__device__ __forceinline__ u64t fma2(u64t a, u64t b, u64t c) {
    u64t d; asm("fma.rn.f32x2 %0, %1, %2, %3;" : "=l"(d) : "l"(a), "l"(b), "l"(c)); return d;
}
__device__ __forceinline__ u64t mul2(u64t a, u64t b) {
    u64t d; asm("mul.rn.f32x2 %0, %1, %2;" : "=l"(d) : "l"(a), "l"(b)); return d;
}
__device__ __forceinline__ u64t add2(u64t a, u64t b) {
    u64t d; asm("add.rn.f32x2 %0, %1, %2;" : "=l"(d) : "l"(a), "l"(b)); return d;
}
__device__ __forceinline__ float ex2f(float x) {
    float r; asm("ex2.approx.f32 %0, %1;" : "=f"(r) : "f"(x)); return r;
}

// ---------------------------------------------------------------------------
// Embed
// ---------------------------------------------------------------------------
__global__ void embed_kernel(const float* __restrict__ x,
                             const float* __restrict__ conv_w,
                             const float* __restrict__ pos_s,
                             const float* __restrict__ pos_h,
                             const float* __restrict__ pos_w)
{
    int idx = blockIdx.x * blockDim.x + threadIdx.x;
    if (idx < Bb) g_logits[idx] = 0.0f;
    if (idx >= NPOS) return;
    int w = idx & 63;
    int t = idx >> 6;
    int h = t & 63;
    t >>= 6;
    int s = t % Ss;
    float xv = x[idx];
    float vals[8];
#pragma unroll
    for (int d = 0; d < 8; d++) {
        float v = fmaxf(xv * conv_w[d], 0.0f);
        v += pos_s[s * 8 + d] + pos_h[d * 64 + h] + pos_w[d * 64 + w];
        vals[d] = v;
    }
    float4* o = (float4*)(g_xt + (long)idx * 8);
    o[0] = make_float4(vals[0], vals[1], vals[2], vals[3]);
    o[1] = make_float4(vals[4], vals[5], vals[6], vals[7]);
}

// ---------------------------------------------------------------------------
// Axial attention, L=64. One thread per (row, head): 256 threads / sequence.
// Dots kept in packed registers -> single read of K, single read of V.
// ---------------------------------------------------------------------------
__global__ void __launch_bounds__(256, 2)
axial_attn64(const float* __restrict__ zin, float* __restrict__ zout,
             const float* __restrict__ Wq, const float* __restrict__ Wkv,
             const float* __restrict__ Wo, const float* __restrict__ bo,
             int inner_count, int outer_mult, int stride, int accum)
{
    __shared__ float sWq[128];
    __shared__ float sWkv[256];
    __shared__ float sWo[128];
    __shared__ float sbo[8];
    __shared__ float sK[4][4][64];    // [h][e][j]
    __shared__ float sV[4][4][64];
    __shared__ float sPart[4][8][64]; // [h][d][i] partial outputs

    const int tid = threadIdx.x;
    const int h   = tid >> 6;     // head 0..3 (warps 2h, 2h+1)
    const int i   = tid & 63;     // row 0..63

    if (tid < 128) sWq[tid] = Wq[tid];
    sWkv[tid] = Wkv[tid];
    if (tid < 128) sWo[tid] = Wo[tid];
    if (tid < 8) sbo[tid] = bo[tid];

    const int seq   = blockIdx.x;
    const int outer = seq / inner_count;
    const int rem   = seq - outer * inner_count;
    const long base = (long)outer * outer_mult + rem;

    const float* zr = zin + (base + (long)i * stride) * 8;
    float4 a0 = *(const float4*)zr;
    float4 a1 = *(const float4*)(zr + 4);
    float row[8] = {a0.x, a0.y, a0.z, a0.w, a1.x, a1.y, a1.z, a1.w};

    __syncthreads();  // weights ready

    // k,v projection for (h, i): 4 e components each
#pragma unroll
    for (int e = 0; e < 4; e++) {
        float sk = 0.0f, sv = 0.0f;
#pragma unroll
        for (int d = 0; d < 8; d++) {
            sk = fmaf(row[d], sWkv[d * 32 + h * 4 + e], sk);
            sv = fmaf(row[d], sWkv[d * 32 + 16 + h * 4 + e], sv);
        }
        sK[h][e][i] = sk;
        sV[h][e][i] = sv;
    }

    // q for (h, i), pre-scaled by 0.5*log2(e), packed (q,q)
    u64t qp[4];
#pragma unroll
    for (int e = 0; e < 4; e++) {
        float s = 0.0f;
#pragma unroll
        for (int d = 0; d < 8; d++) s = fmaf(row[d], sWq[d * 16 + h * 4 + e], s);
        s *= 0.5f * LOG2E;
        qp[e] = pk2(s, s);
    }
    __syncthreads();

    const ulonglong2* K0 = (const ulonglong2*)sK[h][0];
    const ulonglong2* K1 = (const ulonglong2*)sK[h][1];
    const ulonglong2* K2 = (const ulonglong2*)sK[h][2];
    const ulonglong2* K3 = (const ulonglong2*)sK[h][3];
    const ulonglong2* V0 = (const ulonglong2*)sV[h][0];
    const ulonglong2* V1 = (const ulonglong2*)sV[h][1];
    const ulonglong2* V2 = (const ulonglong2*)sV[h][2];
    const ulonglong2* V3 = (const ulonglong2*)sV[h][3];

    // pass 1: dots -> packed registers, running max
    u64t p2[32];
    float m = -1e30f;
#pragma unroll
    for (int jg = 0; jg < 16; jg++) {
        ulonglong2 k0 = K0[jg], k1 = K1[jg], k2 = K2[jg], k3 = K3[jg];
        u64t d01 = mul2(qp[0], k0.x);
        d01 = fma2(qp[1], k1.x, d01);
        d01 = fma2(qp[2], k2.x, d01);
        d01 = fma2(qp[3], k3.x, d01);
        u64t d23 = mul2(qp[0], k0.y);
        d23 = fma2(qp[1], k1.y, d23);
        d23 = fma2(qp[2], k2.y, d23);
        d23 = fma2(qp[3], k3.y, d23);
        p2[2 * jg]     = d01;
        p2[2 * jg + 1] = d23;
        float x0, x1, x2, x3;
        up2(d01, x0, x1);
        up2(d23, x2, x3);
        m = fmaxf(m, fmaxf(fmaxf(x0, x1), fmaxf(x2, x3)));
    }

    // pass 2: exp2(p - m), sum, o accumulation (V read once)
    u64t mneg = pk2(-m, -m);
    u64t s01 = pk2(0.0f, 0.0f);
    u64t o0 = s01, o1 = s01, o2 = s01, o3 = s01;
#pragma unroll
    for (int jg = 0; jg < 16; jg++) {
        u64t t01 = add2(p2[2 * jg], mneg);
        u64t t23 = add2(p2[2 * jg + 1], mneg);
        float x0, x1, x2, x3;
        up2(t01, x0, x1);
        up2(t23, x2, x3);
        float e0 = ex2f(x0), e1 = ex2f(x1), e2 = ex2f(x2), e3 = ex2f(x3);
        u64t e01 = pk2(e0, e1);
        u64t e23 = pk2(e2, e3);
        s01 = add2(s01, e01);
        s01 = add2(s01, e23);
        ulonglong2 v0 = V0[jg], v1 = V1[jg], v2 = V2[jg], v3 = V3[jg];
        o0 = fma2(e01, v0.x, o0); o0 = fma2(e23, v0.y, o0);
        o1 = fma2(e01, v1.x, o1); o1 = fma2(e23, v1.y, o1);
        o2 = fma2(e01, v2.x, o2); o2 = fma2(e23, v2.y, o2);
        o3 = fma2(e01, v3.x, o3); o3 = fma2(e23, v3.y, o3);
    }
    float sa, sb;
    up2(s01, sa, sb);
    float inv = 1.0f / (sa + sb);
    float oe[4];
    {
        float ua, ub;
        up2(o0, ua, ub); oe[0] = (ua + ub) * inv;
        up2(o1, ua, ub); oe[1] = (ua + ub) * inv;
        up2(o2, ua, ub); oe[2] = (ua + ub) * inv;
        up2(o3, ua, ub); oe[3] = (ua + ub) * inv;
    }

    // partial output projection for this head -> shared [h][d][i]
#pragma unroll
    for (int d = 0; d < 8; d++) {
        float s = 0.0f;
#pragma unroll
        for (int e = 0; e < 4; e++) s = fmaf(oe[e], sWo[(h * 4 + e) * 8 + d], s);
        sPart[h][d][i] = s;
    }
    __syncthreads();

    // final reduce across heads: 64 threads, one per row
    if (tid < 64) {
        const int r = tid;
        float outv[8];
#pragma unroll
        for (int d = 0; d < 8; d++) {
            float s = sbo[d];
#pragma unroll
            for (int hh = 0; hh < 4; hh++) s += sPart[hh][d][r];
            outv[d] = s;
        }
        float* zo = zout + (base + (long)r * stride) * 8;
        if (accum) {
            float4 b0 = *(float4*)zo;
            float4 b1 = *(float4*)(zo + 4);
            outv[0] += b0.x; outv[1] += b0.y; outv[2] += b0.z; outv[3] += b0.w;
            outv[4] += b1.x; outv[5] += b1.y; outv[6] += b1.z; outv[7] += b1.w;
        }
        ((float4*)zo)[0] = make_float4(outv[0], outv[1], outv[2], outv[3]);
        ((float4*)zo)[1] = make_float4(outv[4], outv[5], outv[6], outv[7]);
    }
}

// ---------------------------------------------------------------------------
// Axial attention, L=20 (sequence axis).
// ---------------------------------------------------------------------------
template<int L, int NS>
__global__ void __launch_bounds__(L*NS)
axial_attn(const float* __restrict__ zin, float* __restrict__ zout,
           const float* __restrict__ Wq, const float* __restrict__ Wkv,
           const float* __restrict__ Wo, const float* __restrict__ bo,
           int inner_count, int outer_mult, int stride, int accum)
{
    __shared__ float sWq[128];
    __shared__ float sWkv[256];
    __shared__ float sWo[128];
    __shared__ float sbo[8];
    __shared__ float4 sKq[NS][4][L];
    __shared__ float4 sVq[NS][4][L];

    const int i   = threadIdx.x;
    const int sl  = threadIdx.y;
    const int tid = sl * L + i;
    const int nth = L * NS;

    for (int t = tid; t < 128; t += nth) sWq[t]  = Wq[t];
    for (int t = tid; t < 256; t += nth) sWkv[t] = Wkv[t];
    for (int t = tid; t < 128; t += nth) sWo[t]  = Wo[t];
    if (tid < 8) sbo[tid] = bo[tid];

    const int seq   = blockIdx.x * NS + sl;
    const int outer = seq / inner_count;
    const int rem   = seq - outer * inner_count;
    const long base = (long)outer * outer_mult + rem;

    const float* zr = zin + (base + (long)i * stride) * 8;
    float4 a0 = *(const float4*)zr;
    float4 a1 = *(const float4*)(zr + 4);
    float row[8] = {a0.x, a0.y, a0.z, a0.w, a1.x, a1.y, a1.z, a1.w};

    __syncthreads();

    float q[16];
#pragma unroll
    for (int c = 0; c < 16; c++) {
        float s = 0.0f;
#pragma unroll
        for (int d = 0; d < 8; d++) s = fmaf(row[d], sWq[d * 16 + c], s);
        q[c] = s * (0.5f * LOG2E);
    }
#pragma unroll
    for (int h = 0; h < 4; h++) {
        float4 kk, vv;
        float* kp = (float*)&kk;
        float* vp = (float*)&vv;
#pragma unroll
        for (int e = 0; e < 4; e++) {
            float sk = 0.0f, sv = 0.0f;
#pragma unroll
            for (int d = 0; d < 8; d++) {
                sk = fmaf(row[d], sWkv[d * 32 + h * 4 + e], sk);
                sv = fmaf(row[d], sWkv[d * 32 + 16 + h * 4 + e], sv);
            }
            kp[e] = sk; vp[e] = sv;
        }
        sKq[sl][h][i] = kk;
        sVq[sl][h][i] = vv;
    }
    __syncthreads();

    float oacc[16];
#pragma unroll
    for (int h = 0; h < 4; h++) {
        const float qx = q[h*4+0], qy = q[h*4+1], qz = q[h*4+2], qw = q[h*4+3];
        float p[L];
        float m = -1e30f;
#pragma unroll
        for (int j = 0; j < L; j++) {
            float4 kj = sKq[sl][h][j];
            float d = qx*kj.x + qy*kj.y + qz*kj.z + qw*kj.w;
            p[j] = d;
            m = fmaxf(m, d);
        }
        float ssum = 0.0f;
        float ox = 0.f, oy = 0.f, oz = 0.f, ow = 0.f;
#pragma unroll
        for (int j = 0; j < L; j++) {
            float e = ex2f(p[j] - m);
            ssum += e;
            float4 vj = sVq[sl][h][j];
            ox = fmaf(e, vj.x, ox);
            oy = fmaf(e, vj.y, oy);
            oz = fmaf(e, vj.z, oz);
            ow = fmaf(e, vj.w, ow);
        }
        float inv = 1.0f / ssum;
        oacc[h*4+0] = ox * inv;
        oacc[h*4+1] = oy * inv;
        oacc[h*4+2] = oz * inv;
        oacc[h*4+3] = ow * inv;
    }

    float outv[8];
#pragma unroll
    for (int d = 0; d < 8; d++) {
        float s = sbo[d];
#pragma unroll
        for (int c = 0; c < 16; c++) s = fmaf(oacc[c], sWo[c * 8 + d], s);
        outv[d] = s;
    }

    float* zo = zout + (base + (long)i * stride) * 8;
    if (accum) {
        float4 o0 = *(float4*)zo;
        float4 o1 = *(float4*)(zo + 4);
        outv[0] += o0.x; outv[1] += o0.y; outv[2] += o0.z; outv[3] += o0.w;
        outv[4] += o1.x; outv[5] += o1.y; outv[6] += o1.z; outv[7] += o1.w;
    }
    ((float4*)zo)[0] = make_float4(outv[0], outv[1], outv[2], outv[3]);
    ((float4*)zo)[1] = make_float4(outv[4], outv[5], outv[6], outv[7]);
}

// ---------------------------------------------------------------------------
// Epilogue
// ---------------------------------------------------------------------------
__global__ void reduce_kernel(const float* __restrict__ zfin,
                              const float* __restrict__ Wc)
{
    const int b = blockIdx.y;
    const int t = blockIdx.x * blockDim.x + threadIdx.x;
    const int d  = t & 7;
    const int hw = t >> 3;
    long base = (long)b * Ss * 32768 + (long)hw * 8 + d;
    float m = -1e30f;
#pragma unroll
    for (int s = 0; s < Ss; s++) {
        long o = base + (long)s * 32768;
        m = fmaxf(m, zfin[o] + g_xt[o]);
    }
    float val = m * Wc[d * 4096 + hw];

    __shared__ float red[256];
    red[threadIdx.x] = val;
    __syncthreads();
    for (int off = 128; off > 0; off >>= 1) {
        if (threadIdx.x < off) red[threadIdx.x] += red[threadIdx.x + off];
        __syncthreads();
    }
    if (threadIdx.x == 0) atomicAdd(&g_logits[b], red[0]);
}

__global__ void final_kernel(const float* __restrict__ bc, float* __restrict__ out)
{
    int b = threadIdx.x;
    if (b < Bb) {
        float lg = g_logits[b] + bc[0];
        out[b] = 1.0f / (1.0f + __expf(-lg));
    }
}

// ---------------------------------------------------------------------------
extern "C" void kernel_launch(void* const* d_in, const int* in_sizes, int n_in,
                              void* d_out, int out_size)
{
    const float* x      = (const float*)d_in[0];
    const float* conv_w = (const float*)d_in[1];
    const float* pos_s  = (const float*)d_in[2];
    const float* pos_h  = (const float*)d_in[3];
    const float* pos_w  = (const float*)d_in[4];
    const float* Wq     = (const float*)d_in[5];
    const float* Wkv    = (const float*)d_in[6];
    const float* Wo     = (const float*)d_in[7];
    const float* bo     = (const float*)d_in[8];
    const float* Wc     = (const float*)d_in[9];
    const float* bc     = (const float*)d_in[10];
    float* out = (float*)d_out;

    float *pXt = nullptr, *pA = nullptr, *pB = nullptr;
    cudaGetSymbolAddress((void**)&pXt, g_xt);
    cudaGetSymbolAddress((void**)&pA,  g_bufA);
    cudaGetSymbolAddress((void**)&pB,  g_bufB);

    embed_kernel<<<(NPOS + 255) / 256, 256>>>(x, conv_w, pos_s, pos_h, pos_w);

    float* cur = pXt;
    for (int l = 0; l < NLl; l++) {
        float* nxt = (l & 1) ? pB : pA;
        const float* wq0 = Wq  + (l * 3 + 0) * 128;
        const float* wk0 = Wkv + (l * 3 + 0) * 256;
        const float* wo0 = Wo  + (l * 3 + 0) * 128;
        const float* bo0 = bo  + (l * 3 + 0) * 8;

        // axis 1 (S, L=20): write
        {
            dim3 blk(20, 8);
            axial_attn<20, 8><<<Bb * IMm * IMm / 8, blk>>>(
                cur, nxt, wq0, wk0, wo0, bo0,
                IMm * IMm, Ss * IMm * IMm, IMm * IMm, 0);
        }
        // axis 2 (H, L=64): accumulate
        axial_attn64<<<Bb * Ss * IMm, 256>>>(
            cur, nxt, wq0 + 128, wk0 + 256, wo0 + 128, bo0 + 8,
            IMm, IMm * IMm, IMm, 1);
        // axis 3 (W, L=64): accumulate
        axial_attn64<<<Bb * Ss * IMm, 256>>>(
            cur, nxt, wq0 + 256, wk0 + 512, wo0 + 256, bo0 + 16,
            1, IMm, 1, 1);
        cur = nxt;
    }

    {
        dim3 grid(IMm * IMm * Dd / 256, Bb);
        reduce_kernel<<<grid, 256>>>(cur, Wc);
    }
    final_kernel<<<1, 32>>>(bc, out);
}

// round 5
// speedup vs baseline: 1.2151x; 1.2151x over previous
#include <cuda_runtime.h>
#include <math.h>

// Problem constants
#define Bb 4
#define Ss 20
#define IMm 64
#define Dd 8
#define NLl 4
#define NPOS (Bb*Ss*IMm*IMm)
#define NELEM (NPOS*Dd)
#define LOG2E 1.4426950408889634f
#define QSCALE (0.5f * LOG2E)

// Scratch (no allocations allowed)
__device__ float g_xt[NELEM];
__device__ float g_bufA[NELEM];
__device__ float g_bufB[NELEM];
__device__ float g_logits[Bb];

// ---------------- packed f32x2 helpers (sm_103a) ----------------
typedef unsigned long long u64t;
__device__ __forceinline__ u64t pk2(float lo, float hi) {
    u64t r; asm("mov.b64 %0, {%1,%2};" : "=l"(r) : "f"(lo), "f"(hi)); return r;
}
__device__ __forceinline__ void up2(u64t v, float& a, float& b) {
    asm("mov.b64 {%0,%1}, %2;" : "=f"(a), "=f"(b) : "l"(v));
}
__device__ __forceinline__ u64t fma2(u64t a, u64t b, u64t c) {
    u64t d; asm("fma.rn.f32x2 %0, %1, %2, %3;" : "=l"(d) : "l"(a), "l"(b), "l"(c)); return d;
}
__device__ __forceinline__ u64t mul2(u64t a, u64t b) {
    u64t d; asm("mul.rn.f32x2 %0, %1, %2;" : "=l"(d) : "l"(a), "l"(b)); return d;
}
__device__ __forceinline__ u64t add2(u64t a, u64t b) {
    u64t d; asm("add.rn.f32x2 %0, %1, %2;" : "=l"(d) : "l"(a), "l"(b)); return d;
}
__device__ __forceinline__ float ex2f(float x) {
    float r; asm("ex2.approx.f32 %0, %1;" : "=f"(r) : "f"(x)); return r;
}

// ---------------------------------------------------------------------------
// Embed
// ---------------------------------------------------------------------------
__global__ void embed_kernel(const float* __restrict__ x,
                             const float* __restrict__ conv_w,
                             const float* __restrict__ pos_s,
                             const float* __restrict__ pos_h,
                             const float* __restrict__ pos_w)
{
    int idx = blockIdx.x * blockDim.x + threadIdx.x;
    if (idx < Bb) g_logits[idx] = 0.0f;
    if (idx >= NPOS) return;
    int w = idx & 63;
    int t = idx >> 6;
    int h = t & 63;
    t >>= 6;
    int s = t % Ss;
    float xv = x[idx];
    float vals[8];
#pragma unroll
    for (int d = 0; d < 8; d++) {
        float v = fmaxf(xv * conv_w[d], 0.0f);
        v += pos_s[s * 8 + d] + pos_h[d * 64 + h] + pos_w[d * 64 + w];
        vals[d] = v;
    }
    float4* o = (float4*)(g_xt + (long)idx * 8);
    o[0] = make_float4(vals[0], vals[1], vals[2], vals[3]);
    o[1] = make_float4(vals[4], vals[5], vals[6], vals[7]);
}

// ---------------------------------------------------------------------------
// Axial attention, L=64. One thread per (row, head). Single-pass softmax in
// log2 domain WITHOUT max subtraction (args are O(1); exp2 safe to 2^127).
// ---------------------------------------------------------------------------
__global__ void __launch_bounds__(256, 4)
axial_attn64(const float* __restrict__ zin, float* __restrict__ zout,
             const float* __restrict__ Wq, const float* __restrict__ Wkv,
             const float* __restrict__ Wo, const float* __restrict__ bo,
             int inner_count, int outer_mult, int stride, int accum)
{
    __shared__ float  sWq[128];        // pre-scaled by 0.5*log2e
    __shared__ float2 sKV2[8][16];     // [d][h*4+e] = (k_w, v_w)
    __shared__ float  sWo[128];
    __shared__ float  sbo[8];
    __shared__ float  sK[4][4][64];    // [h][e][j]
    __shared__ float  sV[4][4][64];
    __shared__ float  sPart[4][8][64]; // [h][d][i]

    const int tid = threadIdx.x;
    const int h   = tid >> 6;
    const int i   = tid & 63;

    if (tid < 128) sWq[tid] = Wq[tid] * QSCALE;
    if (tid < 128) {
        int d = tid >> 4, c = tid & 15;
        sKV2[d][c] = make_float2(Wkv[d * 32 + c], Wkv[d * 32 + 16 + c]);
    }
    if (tid < 128) sWo[tid] = Wo[tid];
    if (tid < 8) sbo[tid] = bo[tid];

    const int seq   = blockIdx.x;
    const int outer = seq / inner_count;
    const int rem   = seq - outer * inner_count;
    const long base = (long)outer * outer_mult + rem;

    const float* zr = zin + (base + (long)i * stride) * 8;
    float4 a0 = *(const float4*)zr;
    float4 a1 = *(const float4*)(zr + 4);
    float row[8] = {a0.x, a0.y, a0.z, a0.w, a1.x, a1.y, a1.z, a1.w};
    u64t rp[8];
#pragma unroll
    for (int d = 0; d < 8; d++) rp[d] = pk2(row[d], row[d]);

    __syncthreads();  // weights ready

    // k,v projection (packed over (k,v)) -> shared
    const u64t* kvw = (const u64t*)&sKV2[0][0];
#pragma unroll
    for (int e = 0; e < 4; e++) {
        u64t acc = mul2(rp[0], kvw[0 * 16 + h * 4 + e]);
#pragma unroll
        for (int d = 1; d < 8; d++) acc = fma2(rp[d], kvw[d * 16 + h * 4 + e], acc);
        float sk, sv;
        up2(acc, sk, sv);
        sK[h][e][i] = sk;
        sV[h][e][i] = sv;
    }

    // q projection (pre-scaled), packed (q,q)
    u64t qp[4];
#pragma unroll
    for (int e = 0; e < 4; e++) {
        float s = 0.0f;
#pragma unroll
        for (int d = 0; d < 8; d++) s = fmaf(row[d], sWq[d * 16 + h * 4 + e], s);
        qp[e] = pk2(s, s);
    }
    __syncthreads();

    const ulonglong2* K0 = (const ulonglong2*)sK[h][0];
    const ulonglong2* K1 = (const ulonglong2*)sK[h][1];
    const ulonglong2* K2 = (const ulonglong2*)sK[h][2];
    const ulonglong2* K3 = (const ulonglong2*)sK[h][3];
    const ulonglong2* V0 = (const ulonglong2*)sV[h][0];
    const ulonglong2* V1 = (const ulonglong2*)sV[h][1];
    const ulonglong2* V2 = (const ulonglong2*)sV[h][2];
    const ulonglong2* V3 = (const ulonglong2*)sV[h][3];

    // single pass: dot (log2 domain) -> exp2 -> sum & o accumulation
    u64t s01 = pk2(0.0f, 0.0f);
    u64t o0 = s01, o1 = s01, o2 = s01, o3 = s01;
#pragma unroll
    for (int jg = 0; jg < 16; jg++) {
        ulonglong2 k0 = K0[jg], k1 = K1[jg], k2 = K2[jg], k3 = K3[jg];
        u64t d01 = mul2(qp[0], k0.x);
        d01 = fma2(qp[1], k1.x, d01);
        d01 = fma2(qp[2], k2.x, d01);
        d01 = fma2(qp[3], k3.x, d01);
        u64t d23 = mul2(qp[0], k0.y);
        d23 = fma2(qp[1], k1.y, d23);
        d23 = fma2(qp[2], k2.y, d23);
        d23 = fma2(qp[3], k3.y, d23);
        float x0, x1, x2, x3;
        up2(d01, x0, x1);
        up2(d23, x2, x3);
        float e0 = ex2f(x0), e1 = ex2f(x1), e2 = ex2f(x2), e3 = ex2f(x3);
        u64t e01 = pk2(e0, e1);
        u64t e23 = pk2(e2, e3);
        s01 = add2(s01, e01);
        s01 = add2(s01, e23);
        ulonglong2 v0 = V0[jg], v1 = V1[jg], v2 = V2[jg], v3 = V3[jg];
        o0 = fma2(e01, v0.x, o0); o0 = fma2(e23, v0.y, o0);
        o1 = fma2(e01, v1.x, o1); o1 = fma2(e23, v1.y, o1);
        o2 = fma2(e01, v2.x, o2); o2 = fma2(e23, v2.y, o2);
        o3 = fma2(e01, v3.x, o3); o3 = fma2(e23, v3.y, o3);
    }
    float sa, sb;
    up2(s01, sa, sb);
    float inv = 1.0f / (sa + sb);
    float oe[4];
    {
        float ua, ub;
        up2(o0, ua, ub); oe[0] = (ua + ub) * inv;
        up2(o1, ua, ub); oe[1] = (ua + ub) * inv;
        up2(o2, ua, ub); oe[2] = (ua + ub) * inv;
        up2(o3, ua, ub); oe[3] = (ua + ub) * inv;
    }

    // partial output projection for this head -> shared [h][d][i]
#pragma unroll
    for (int d = 0; d < 8; d++) {
        float s = 0.0f;
#pragma unroll
        for (int e = 0; e < 4; e++) s = fmaf(oe[e], sWo[(h * 4 + e) * 8 + d], s);
        sPart[h][d][i] = s;
    }
    __syncthreads();

    // final reduce across heads: 64 threads, one per row
    if (tid < 64) {
        const int r = tid;
        float outv[8];
#pragma unroll
        for (int d = 0; d < 8; d++) {
            float s = sbo[d];
#pragma unroll
            for (int hh = 0; hh < 4; hh++) s += sPart[hh][d][r];
            outv[d] = s;
        }
        float* zo = zout + (base + (long)r * stride) * 8;
        if (accum) {
            float4 b0 = *(float4*)zo;
            float4 b1 = *(float4*)(zo + 4);
            outv[0] += b0.x; outv[1] += b0.y; outv[2] += b0.z; outv[3] += b0.w;
            outv[4] += b1.x; outv[5] += b1.y; outv[6] += b1.z; outv[7] += b1.w;
        }
        ((float4*)zo)[0] = make_float4(outv[0], outv[1], outv[2], outv[3]);
        ((float4*)zo)[1] = make_float4(outv[4], outv[5], outv[6], outv[7]);
    }
}

// ---------------------------------------------------------------------------
// Axial attention, L=20 (sequence axis). Single pass, no max.
// ---------------------------------------------------------------------------
template<int L, int NS>
__global__ void __launch_bounds__(L*NS)
axial_attn(const float* __restrict__ zin, float* __restrict__ zout,
           const float* __restrict__ Wq, const float* __restrict__ Wkv,
           const float* __restrict__ Wo, const float* __restrict__ bo,
           int inner_count, int outer_mult, int stride, int accum)
{
    __shared__ float sWq[128];     // pre-scaled
    __shared__ float sWkv[256];
    __shared__ float sWo[128];
    __shared__ float sbo[8];
    __shared__ float4 sKq[NS][4][L];
    __shared__ float4 sVq[NS][4][L];

    const int i   = threadIdx.x;
    const int sl  = threadIdx.y;
    const int tid = sl * L + i;
    const int nth = L * NS;

    for (int t = tid; t < 128; t += nth) sWq[t]  = Wq[t] * QSCALE;
    for (int t = tid; t < 256; t += nth) sWkv[t] = Wkv[t];
    for (int t = tid; t < 128; t += nth) sWo[t]  = Wo[t];
    if (tid < 8) sbo[tid] = bo[tid];

    const int seq   = blockIdx.x * NS + sl;
    const int outer = seq / inner_count;
    const int rem   = seq - outer * inner_count;
    const long base = (long)outer * outer_mult + rem;

    const float* zr = zin + (base + (long)i * stride) * 8;
    float4 a0 = *(const float4*)zr;
    float4 a1 = *(const float4*)(zr + 4);
    float row[8] = {a0.x, a0.y, a0.z, a0.w, a1.x, a1.y, a1.z, a1.w};

    __syncthreads();

    float q[16];
#pragma unroll
    for (int c = 0; c < 16; c++) {
        float s = 0.0f;
#pragma unroll
        for (int d = 0; d < 8; d++) s = fmaf(row[d], sWq[d * 16 + c], s);
        q[c] = s;
    }
#pragma unroll
    for (int h = 0; h < 4; h++) {
        float4 kk, vv;
        float* kp = (float*)&kk;
        float* vp = (float*)&vv;
#pragma unroll
        for (int e = 0; e < 4; e++) {
            float sk = 0.0f, sv = 0.0f;
#pragma unroll
            for (int d = 0; d < 8; d++) {
                sk = fmaf(row[d], sWkv[d * 32 + h * 4 + e], sk);
                sv = fmaf(row[d], sWkv[d * 32 + 16 + h * 4 + e], sv);
            }
            kp[e] = sk; vp[e] = sv;
        }
        sKq[sl][h][i] = kk;
        sVq[sl][h][i] = vv;
    }
    __syncthreads();

    float oacc[16];
#pragma unroll
    for (int h = 0; h < 4; h++) {
        const float qx = q[h*4+0], qy = q[h*4+1], qz = q[h*4+2], qw = q[h*4+3];
        float ssum = 0.0f;
        float ox = 0.f, oy = 0.f, oz = 0.f, ow = 0.f;
#pragma unroll
        for (int j = 0; j < L; j++) {
            float4 kj = sKq[sl][h][j];
            float d = qx*kj.x + qy*kj.y + qz*kj.z + qw*kj.w;
            float e = ex2f(d);
            ssum += e;
            float4 vj = sVq[sl][h][j];
            ox = fmaf(e, vj.x, ox);
            oy = fmaf(e, vj.y, oy);
            oz = fmaf(e, vj.z, oz);
            ow = fmaf(e, vj.w, ow);
        }
        float inv = 1.0f / ssum;
        oacc[h*4+0] = ox * inv;
        oacc[h*4+1] = oy * inv;
        oacc[h*4+2] = oz * inv;
        oacc[h*4+3] = ow * inv;
    }

    float outv[8];
#pragma unroll
    for (int d = 0; d < 8; d++) {
        float s = sbo[d];
#pragma unroll
        for (int c = 0; c < 16; c++) s = fmaf(oacc[c], sWo[c * 8 + d], s);
        outv[d] = s;
    }

    float* zo = zout + (base + (long)i * stride) * 8;
    if (accum) {
        float4 o0 = *(float4*)zo;
        float4 o1 = *(float4*)(zo + 4);
        outv[0] += o0.x; outv[1] += o0.y; outv[2] += o0.z; outv[3] += o0.w;
        outv[4] += o1.x; outv[5] += o1.y; outv[6] += o1.z; outv[7] += o1.w;
    }
    ((float4*)zo)[0] = make_float4(outv[0], outv[1], outv[2], outv[3]);
    ((float4*)zo)[1] = make_float4(outv[4], outv[5], outv[6], outv[7]);
}

// ---------------------------------------------------------------------------
// Epilogue
// ---------------------------------------------------------------------------
__global__ void reduce_kernel(const float* __restrict__ zfin,
                              const float* __restrict__ Wc)
{
    const int b = blockIdx.y;
    const int t = blockIdx.x * blockDim.x + threadIdx.x;
    const int d  = t & 7;
    const int hw = t >> 3;
    long base = (long)b * Ss * 32768 + (long)hw * 8 + d;
    float m = -1e30f;
#pragma unroll
    for (int s = 0; s < Ss; s++) {
        long o = base + (long)s * 32768;
        m = fmaxf(m, zfin[o] + g_xt[o]);
    }
    float val = m * Wc[d * 4096 + hw];

    __shared__ float red[256];
    red[threadIdx.x] = val;
    __syncthreads();
    for (int off = 128; off > 0; off >>= 1) {
        if (threadIdx.x < off) red[threadIdx.x] += red[threadIdx.x + off];
        __syncthreads();
    }
    if (threadIdx.x == 0) atomicAdd(&g_logits[b], red[0]);
}

__global__ void final_kernel(const float* __restrict__ bc, float* __restrict__ out)
{
    int b = threadIdx.x;
    if (b < Bb) {
        float lg = g_logits[b] + bc[0];
        out[b] = 1.0f / (1.0f + __expf(-lg));
    }
}

// ---------------------------------------------------------------------------
extern "C" void kernel_launch(void* const* d_in, const int* in_sizes, int n_in,
                              void* d_out, int out_size)
{
    const float* x      = (const float*)d_in[0];
    const float* conv_w = (const float*)d_in[1];
    const float* pos_s  = (const float*)d_in[2];
    const float* pos_h  = (const float*)d_in[3];
    const float* pos_w  = (const float*)d_in[4];
    const float* Wq     = (const float*)d_in[5];
    const float* Wkv    = (const float*)d_in[6];
    const float* Wo     = (const float*)d_in[7];
    const float* bo     = (const float*)d_in[8];
    const float* Wc     = (const float*)d_in[9];
    const float* bc     = (const float*)d_in[10];
    float* out = (float*)d_out;

    float *pXt = nullptr, *pA = nullptr, *pB = nullptr;
    cudaGetSymbolAddress((void**)&pXt, g_xt);
    cudaGetSymbolAddress((void**)&pA,  g_bufA);
    cudaGetSymbolAddress((void**)&pB,  g_bufB);

    embed_kernel<<<(NPOS + 255) / 256, 256>>>(x, conv_w, pos_s, pos_h, pos_w);

    float* cur = pXt;
    for (int l = 0; l < NLl; l++) {
        float* nxt = (l & 1) ? pB : pA;
        const float* wq0 = Wq  + (l * 3 + 0) * 128;
        const float* wk0 = Wkv + (l * 3 + 0) * 256;
        const float* wo0 = Wo  + (l * 3 + 0) * 128;
        const float* bo0 = bo  + (l * 3 + 0) * 8;

        // axis 1 (S, L=20): write
        {
            dim3 blk(20, 8);
            axial_attn<20, 8><<<Bb * IMm * IMm / 8, blk>>>(
                cur, nxt, wq0, wk0, wo0, bo0,
                IMm * IMm, Ss * IMm * IMm, IMm * IMm, 0);
        }
        // axis 2 (H, L=64): accumulate
        axial_attn64<<<Bb * Ss * IMm, 256>>>(
            cur, nxt, wq0 + 128, wk0 + 256, wo0 + 128, bo0 + 8,
            IMm, IMm * IMm, IMm, 1);
        // axis 3 (W, L=64): accumulate
        axial_attn64<<<Bb * Ss * IMm, 256>>>(
            cur, nxt, wq0 + 256, wk0 + 512, wo0 + 256, bo0 + 16,
            1, IMm, 1, 1);
        cur = nxt;
    }

    {
        dim3 grid(IMm * IMm * Dd / 256, Bb);
        reduce_kernel<<<grid, 256>>>(cur, Wc);
    }
    final_kernel<<<1, 32>>>(bc, out);
}

// round 7
// speedup vs baseline: 1.2345x; 1.0159x over previous
#include <cuda_runtime.h>
#include <math.h>

// Problem constants
#define Bb 4
#define Ss 20
#define IMm 64
#define Dd 8
#define NLl 4
#define NPOS (Bb*Ss*IMm*IMm)
#define NELEM (NPOS*Dd)
#define LOG2E 1.4426950408889634f
#define QSCALE (0.5f * LOG2E)

// Scratch (no allocations allowed)
__device__ float g_xt[NELEM];
__device__ float g_bufA[NELEM];
__device__ float g_bufB[NELEM];
__device__ float g_logits[Bb];

// ---------------- packed f32x2 helpers (sm_103a) ----------------
typedef unsigned long long u64t;
__device__ __forceinline__ u64t pk2(float lo, float hi) {
    u64t r; asm("mov.b64 %0, {%1,%2};" : "=l"(r) : "f"(lo), "f"(hi)); return r;
}
__device__ __forceinline__ void up2(u64t v, float& a, float& b) {
    asm("mov.b64 {%0,%1}, %2;" : "=f"(a), "=f"(b) : "l"(v));
}
__device__ __forceinline__ u64t fma2(u64t a, u64t b, u64t c) {
    u64t d; asm("fma.rn.f32x2 %0, %1, %2, %3;" : "=l"(d) : "l"(a), "l"(b), "l"(c)); return d;
}
__device__ __forceinline__ u64t mul2(u64t a, u64t b) {
    u64t d; asm("mul.rn.f32x2 %0, %1, %2;" : "=l"(d) : "l"(a), "l"(b)); return d;
}
__device__ __forceinline__ u64t add2(u64t a, u64t b) {
    u64t d; asm("add.rn.f32x2 %0, %1, %2;" : "=l"(d) : "l"(a), "l"(b)); return d;
}
__device__ __forceinline__ float ex2f(float x) {
    float r; asm("ex2.approx.f32 %0, %1;" : "=f"(r) : "f"(x)); return r;
}

// ---------------------------------------------------------------------------
// Embed
// ---------------------------------------------------------------------------
__global__ void embed_kernel(const float* __restrict__ x,
                             const float* __restrict__ conv_w,
                             const float* __restrict__ pos_s,
                             const float* __restrict__ pos_h,
                             const float* __restrict__ pos_w)
{
    int idx = blockIdx.x * blockDim.x + threadIdx.x;
    if (idx < Bb) g_logits[idx] = 0.0f;
    if (idx >= NPOS) return;
    int w = idx & 63;
    int t = idx >> 6;
    int h = t & 63;
    t >>= 6;
    int s = t % Ss;
    float xv = x[idx];
    float vals[8];
#pragma unroll
    for (int d = 0; d < 8; d++) {
        float v = fmaxf(xv * conv_w[d], 0.0f);
        v += pos_s[s * 8 + d] + pos_h[d * 64 + h] + pos_w[d * 64 + w];
        vals[d] = v;
    }
    float4* o = (float4*)(g_xt + (long)idx * 8);
    o[0] = make_float4(vals[0], vals[1], vals[2], vals[3]);
    o[1] = make_float4(vals[4], vals[5], vals[6], vals[7]);
}

// ---------------------------------------------------------------------------
// Axial attention, L=64. 128 threads = 4 heads x 32 lanes. Each thread
// handles TWO rows (i, i+32) of its head -> K/V smem reads amortized 2x.
// Single-pass softmax in log2 domain (no max; args O(1), exp2 safe).
// ---------------------------------------------------------------------------
__global__ void __launch_bounds__(128, 4)
axial_attn64(const float* __restrict__ zin, float* __restrict__ zout,
             const float* __restrict__ Wq, const float* __restrict__ Wkv,
             const float* __restrict__ Wo, const float* __restrict__ bo,
             int inner_count, int outer_mult, int stride, int accum)
{
    __shared__ float  sWq[128];        // pre-scaled by 0.5*log2e
    __shared__ float2 sKV2[8][16];     // [d][h*4+e] = (k_w, v_w)
    __shared__ float  sWo[128];
    __shared__ float  sbo[8];
    __shared__ __align__(16) float sK[4][4][64];   // [h][e][j]
    __shared__ __align__(16) float sV[4][4][64];
    __shared__ float  sPart[4][8][64]; // [h][d][row]

    const int tid = threadIdx.x;      // 0..127
    const int h   = tid >> 5;         // head
    const int i0  = tid & 31;         // lane: rows i0 and i0+32

    sWq[tid] = Wq[tid] * QSCALE;
    {
        int d = tid >> 4, c = tid & 15;
        sKV2[d][c] = make_float2(Wkv[d * 32 + c], Wkv[d * 32 + 16 + c]);
    }
    sWo[tid] = Wo[tid];
    if (tid < 8) sbo[tid] = bo[tid];

    const int seq   = blockIdx.x;
    const int outer = seq / inner_count;
    const int rem   = seq - outer * inner_count;
    const long base = (long)outer * outer_mult + rem;

    // load my two rows
    const float* zrA = zin + (base + (long)i0 * stride) * 8;
    const float* zrB = zin + (base + (long)(i0 + 32) * stride) * 8;
    float4 aA0 = *(const float4*)zrA;
    float4 aA1 = *(const float4*)(zrA + 4);
    float4 aB0 = *(const float4*)zrB;
    float4 aB1 = *(const float4*)(zrB + 4);
    float rowA[8] = {aA0.x, aA0.y, aA0.z, aA0.w, aA1.x, aA1.y, aA1.z, aA1.w};
    float rowB[8] = {aB0.x, aB0.y, aB0.z, aB0.w, aB1.x, aB1.y, aB1.z, aB1.w};

    __syncthreads();  // weights ready

    // k,v projection (packed over (k,v)) for both rows -> shared
    const u64t* kvw = (const u64t*)&sKV2[0][0];
#pragma unroll
    for (int e = 0; e < 4; e++) {
        u64t wA = kvw[0 * 16 + h * 4 + e];
        u64t accA = mul2(pk2(rowA[0], rowA[0]), wA);
        u64t accB = mul2(pk2(rowB[0], rowB[0]), wA);
#pragma unroll
        for (int d = 1; d < 8; d++) {
            u64t w = kvw[d * 16 + h * 4 + e];
            accA = fma2(pk2(rowA[d], rowA[d]), w, accA);
            accB = fma2(pk2(rowB[d], rowB[d]), w, accB);
        }
        float kA, vA, kB, vB;
        up2(accA, kA, vA);
        up2(accB, kB, vB);
        sK[h][e][i0]      = kA;  sV[h][e][i0]      = vA;
        sK[h][e][i0 + 32] = kB;  sV[h][e][i0 + 32] = vB;
    }

    // q projection (pre-scaled) for both rows
    u64t qpA[4], qpB[4];
#pragma unroll
    for (int e = 0; e < 4; e++) {
        float sA = 0.0f, sB = 0.0f;
#pragma unroll
        for (int d = 0; d < 8; d++) {
            float w = sWq[d * 16 + h * 4 + e];
            sA = fmaf(rowA[d], w, sA);
            sB = fmaf(rowB[d], w, sB);
        }
        qpA[e] = pk2(sA, sA);
        qpB[e] = pk2(sB, sB);
    }
    __syncthreads();

    const ulonglong2* K0 = (const ulonglong2*)sK[h][0];
    const ulonglong2* K1 = (const ulonglong2*)sK[h][1];
    const ulonglong2* K2 = (const ulonglong2*)sK[h][2];
    const ulonglong2* K3 = (const ulonglong2*)sK[h][3];
    const ulonglong2* V0 = (const ulonglong2*)sV[h][0];
    const ulonglong2* V1 = (const ulonglong2*)sV[h][1];
    const ulonglong2* V2 = (const ulonglong2*)sV[h][2];
    const ulonglong2* V3 = (const ulonglong2*)sV[h][3];

    u64t zero = pk2(0.0f, 0.0f);
    u64t sAp = zero, sBp = zero;
    u64t oA0 = zero, oA1 = zero, oA2 = zero, oA3 = zero;
    u64t oB0 = zero, oB1 = zero, oB2 = zero, oB3 = zero;
#pragma unroll
    for (int jg = 0; jg < 16; jg++) {
        ulonglong2 k0 = K0[jg], k1 = K1[jg], k2 = K2[jg], k3 = K3[jg];
        // row A dots
        u64t dA01 = mul2(qpA[0], k0.x);
        dA01 = fma2(qpA[1], k1.x, dA01);
        dA01 = fma2(qpA[2], k2.x, dA01);
        dA01 = fma2(qpA[3], k3.x, dA01);
        u64t dA23 = mul2(qpA[0], k0.y);
        dA23 = fma2(qpA[1], k1.y, dA23);
        dA23 = fma2(qpA[2], k2.y, dA23);
        dA23 = fma2(qpA[3], k3.y, dA23);
        // row B dots
        u64t dB01 = mul2(qpB[0], k0.x);
        dB01 = fma2(qpB[1], k1.x, dB01);
        dB01 = fma2(qpB[2], k2.x, dB01);
        dB01 = fma2(qpB[3], k3.x, dB01);
        u64t dB23 = mul2(qpB[0], k0.y);
        dB23 = fma2(qpB[1], k1.y, dB23);
        dB23 = fma2(qpB[2], k2.y, dB23);
        dB23 = fma2(qpB[3], k3.y, dB23);
        float xa0, xa1, xa2, xa3, xb0, xb1, xb2, xb3;
        up2(dA01, xa0, xa1); up2(dA23, xa2, xa3);
        up2(dB01, xb0, xb1); up2(dB23, xb2, xb3);
        u64t eA01 = pk2(ex2f(xa0), ex2f(xa1));
        u64t eA23 = pk2(ex2f(xa2), ex2f(xa3));
        u64t eB01 = pk2(ex2f(xb0), ex2f(xb1));
        u64t eB23 = pk2(ex2f(xb2), ex2f(xb3));
        sAp = add2(add2(sAp, eA01), eA23);
        sBp = add2(add2(sBp, eB01), eB23);
        ulonglong2 v0 = V0[jg], v1 = V1[jg], v2 = V2[jg], v3 = V3[jg];
        oA0 = fma2(eA01, v0.x, oA0); oA0 = fma2(eA23, v0.y, oA0);
        oA1 = fma2(eA01, v1.x, oA1); oA1 = fma2(eA23, v1.y, oA1);
        oA2 = fma2(eA01, v2.x, oA2); oA2 = fma2(eA23, v2.y, oA2);
        oA3 = fma2(eA01, v3.x, oA3); oA3 = fma2(eA23, v3.y, oA3);
        oB0 = fma2(eB01, v0.x, oB0); oB0 = fma2(eB23, v0.y, oB0);
        oB1 = fma2(eB01, v1.x, oB1); oB1 = fma2(eB23, v1.y, oB1);
        oB2 = fma2(eB01, v2.x, oB2); oB2 = fma2(eB23, v2.y, oB2);
        oB3 = fma2(eB01, v3.x, oB3); oB3 = fma2(eB23, v3.y, oB3);
    }

    float ua, ub, oeA[4], oeB[4];
    up2(sAp, ua, ub);
    float invA = 1.0f / (ua + ub);
    up2(sBp, ua, ub);
    float invB = 1.0f / (ua + ub);
    up2(oA0, ua, ub); oeA[0] = (ua + ub) * invA;
    up2(oA1, ua, ub); oeA[1] = (ua + ub) * invA;
    up2(oA2, ua, ub); oeA[2] = (ua + ub) * invA;
    up2(oA3, ua, ub); oeA[3] = (ua + ub) * invA;
    up2(oB0, ua, ub); oeB[0] = (ua + ub) * invB;
    up2(oB1, ua, ub); oeB[1] = (ua + ub) * invB;
    up2(oB2, ua, ub); oeB[2] = (ua + ub) * invB;
    up2(oB3, ua, ub); oeB[3] = (ua + ub) * invB;

    // partial output projection for this head -> sPart
#pragma unroll
    for (int d = 0; d < 8; d++) {
        float w0 = sWo[(h * 4 + 0) * 8 + d];
        float w1 = sWo[(h * 4 + 1) * 8 + d];
        float w2 = sWo[(h * 4 + 2) * 8 + d];
        float w3 = sWo[(h * 4 + 3) * 8 + d];
        sPart[h][d][i0]      = oeA[0]*w0 + oeA[1]*w1 + oeA[2]*w2 + oeA[3]*w3;
        sPart[h][d][i0 + 32] = oeB[0]*w0 + oeB[1]*w1 + oeB[2]*w2 + oeB[3]*w3;
    }
    __syncthreads();

    // final: 128 threads, (row, dhalf) = (tid>>1, tid&1)
    {
        const int row = tid >> 1;
        const int dh  = (tid & 1) * 4;
        float o0 = sbo[dh+0], o1 = sbo[dh+1], o2 = sbo[dh+2], o3 = sbo[dh+3];
#pragma unroll
        for (int hh = 0; hh < 4; hh++) {
            o0 += sPart[hh][dh+0][row];
            o1 += sPart[hh][dh+1][row];
            o2 += sPart[hh][dh+2][row];
            o3 += sPart[hh][dh+3][row];
        }
        float* zo = zout + (base + (long)row * stride) * 8 + dh;
        if (accum) {
            float4 prev = *(float4*)zo;
            o0 += prev.x; o1 += prev.y; o2 += prev.z; o3 += prev.w;
        }
        *(float4*)zo = make_float4(o0, o1, o2, o3);
    }
}

// ---------------------------------------------------------------------------
// Axial attention, L=20 (sequence axis). One thread per (row, head).
// Heads padded to 32 lanes (warp-aligned broadcasts); NS sequences per block.
// ---------------------------------------------------------------------------
template<int NS>
__global__ void __launch_bounds__(128*NS, 4)
axial_attn20(const float* __restrict__ zin, float* __restrict__ zout,
             const float* __restrict__ Wq, const float* __restrict__ Wkv,
             const float* __restrict__ Wo, const float* __restrict__ bo,
             int inner_count, int outer_mult, int stride, int accum)
{
    __shared__ float  sWq[128];
    __shared__ float2 sKV2[8][16];
    __shared__ float  sWo[128];
    __shared__ float  sbo[8];
    __shared__ __align__(16) float sK[NS][4][4][20];
    __shared__ __align__(16) float sV[NS][4][4][20];
    __shared__ float  sPart[NS][4][8][20];

    const int tid = threadIdx.x;
    const int sl  = tid >> 7;          // sequence slot
    const int h   = (tid >> 5) & 3;    // head
    const int i   = tid & 31;          // row lane (active if < 20)
    const bool active = (i < 20);

    if (tid < 128) sWq[tid] = Wq[tid] * QSCALE;
    if (tid < 128) {
        int d = tid >> 4, c = tid & 15;
        sKV2[d][c] = make_float2(Wkv[d * 32 + c], Wkv[d * 32 + 16 + c]);
    }
    if (tid < 128) sWo[tid] = Wo[tid];
    if (tid < 8) sbo[tid] = bo[tid];

    const int seq   = blockIdx.x * NS + sl;
    const int outer = seq / inner_count;
    const int rem   = seq - outer * inner_count;
    const long base = (long)outer * outer_mult + rem;

    float row[8];
    if (active) {
        const float* zr = zin + (base + (long)i * stride) * 8;
        float4 a0 = *(const float4*)zr;
        float4 a1 = *(const float4*)(zr + 4);
        row[0]=a0.x; row[1]=a0.y; row[2]=a0.z; row[3]=a0.w;
        row[4]=a1.x; row[5]=a1.y; row[6]=a1.z; row[7]=a1.w;
    }
    __syncthreads();

    u64t qp[4];
    if (active) {
        const u64t* kvw = (const u64t*)&sKV2[0][0];
#pragma unroll
        for (int e = 0; e < 4; e++) {
            u64t acc = mul2(pk2(row[0], row[0]), kvw[0 * 16 + h * 4 + e]);
#pragma unroll
            for (int d = 1; d < 8; d++)
                acc = fma2(pk2(row[d], row[d]), kvw[d * 16 + h * 4 + e], acc);
            float sk, sv;
            up2(acc, sk, sv);
            sK[sl][h][e][i] = sk;
            sV[sl][h][e][i] = sv;
        }
#pragma unroll
        for (int e = 0; e < 4; e++) {
            float s = 0.0f;
#pragma unroll
            for (int d = 0; d < 8; d++) s = fmaf(row[d], sWq[d * 16 + h * 4 + e], s);
            qp[e] = pk2(s, s);
        }
    }
    __syncthreads();

    if (active) {
        const ulonglong2* K0 = (const ulonglong2*)sK[sl][h][0];
        const ulonglong2* K1 = (const ulonglong2*)sK[sl][h][1];
        const ulonglong2* K2 = (const ulonglong2*)sK[sl][h][2];
        const ulonglong2* K3 = (const ulonglong2*)sK[sl][h][3];
        const ulonglong2* V0 = (const ulonglong2*)sV[sl][h][0];
        const ulonglong2* V1 = (const ulonglong2*)sV[sl][h][1];
        const ulonglong2* V2 = (const ulonglong2*)sV[sl][h][2];
        const ulonglong2* V3 = (const ulonglong2*)sV[sl][h][3];

        u64t zero = pk2(0.0f, 0.0f);
        u64t s01 = zero, o0 = zero, o1 = zero, o2 = zero, o3 = zero;
#pragma unroll
        for (int jg = 0; jg < 5; jg++) {
            ulonglong2 k0 = K0[jg], k1 = K1[jg], k2 = K2[jg], k3 = K3[jg];
            u64t d01 = mul2(qp[0], k0.x);
            d01 = fma2(qp[1], k1.x, d01);
            d01 = fma2(qp[2], k2.x, d01);
            d01 = fma2(qp[3], k3.x, d01);
            u64t d23 = mul2(qp[0], k0.y);
            d23 = fma2(qp[1], k1.y, d23);
            d23 = fma2(qp[2], k2.y, d23);
            d23 = fma2(qp[3], k3.y, d23);
            float x0, x1, x2, x3;
            up2(d01, x0, x1);
            up2(d23, x2, x3);
            u64t e01 = pk2(ex2f(x0), ex2f(x1));
            u64t e23 = pk2(ex2f(x2), ex2f(x3));
            s01 = add2(add2(s01, e01), e23);
            ulonglong2 v0 = V0[jg], v1 = V1[jg], v2 = V2[jg], v3 = V3[jg];
            o0 = fma2(e01, v0.x, o0); o0 = fma2(e23, v0.y, o0);
            o1 = fma2(e01, v1.x, o1); o1 = fma2(e23, v1.y, o1);
            o2 = fma2(e01, v2.x, o2); o2 = fma2(e23, v2.y, o2);
            o3 = fma2(e01, v3.x, o3); o3 = fma2(e23, v3.y, o3);
        }
        float sa, sb;
        up2(s01, sa, sb);
        float inv = 1.0f / (sa + sb);
        float oe[4];
        {
            float ua, ub;
            up2(o0, ua, ub); oe[0] = (ua + ub) * inv;
            up2(o1, ua, ub); oe[1] = (ua + ub) * inv;
            up2(o2, ua, ub); oe[2] = (ua + ub) * inv;
            up2(o3, ua, ub); oe[3] = (ua + ub) * inv;
        }
#pragma unroll
        for (int d = 0; d < 8; d++) {
            float s = oe[0] * sWo[(h * 4 + 0) * 8 + d]
                    + oe[1] * sWo[(h * 4 + 1) * 8 + d]
                    + oe[2] * sWo[(h * 4 + 2) * 8 + d]
                    + oe[3] * sWo[(h * 4 + 3) * 8 + d];
            sPart[sl][h][d][i] = s;
        }
    }
    __syncthreads();

    // final: NS*40 tasks: (slot, row, dhalf)
    if (tid < NS * 40) {
        const int sl2 = tid / 40;
        const int r2  = tid - sl2 * 40;
        const int row = r2 >> 1;
        const int dh  = (r2 & 1) * 4;
        const int seq2   = blockIdx.x * NS + sl2;
        const int outer2 = seq2 / inner_count;
        const int rem2   = seq2 - outer2 * inner_count;
        const long base2 = (long)outer2 * outer_mult + rem2;

        float o0 = sbo[dh+0], o1 = sbo[dh+1], o2 = sbo[dh+2], o3 = sbo[dh+3];
#pragma unroll
        for (int hh = 0; hh < 4; hh++) {
            o0 += sPart[sl2][hh][dh+0][row];
            o1 += sPart[sl2][hh][dh+1][row];
            o2 += sPart[sl2][hh][dh+2][row];
            o3 += sPart[sl2][hh][dh+3][row];
        }
        float* zo = zout + (base2 + (long)row * stride) * 8 + dh;
        if (accum) {
            float4 prev = *(float4*)zo;
            o0 += prev.x; o1 += prev.y; o2 += prev.z; o3 += prev.w;
        }
        *(float4*)zo = make_float4(o0, o1, o2, o3);
    }
}

// ---------------------------------------------------------------------------
// Epilogue
// ---------------------------------------------------------------------------
__global__ void reduce_kernel(const float* __restrict__ zfin,
                              const float* __restrict__ Wc)
{
    const int b = blockIdx.y;
    const int t = blockIdx.x * blockDim.x + threadIdx.x;
    const int d  = t & 7;
    const int hw = t >> 3;
    long base = (long)b * Ss * 32768 + (long)hw * 8 + d;
    float m = -1e30f;
#pragma unroll
    for (int s = 0; s < Ss; s++) {
        long o = base + (long)s * 32768;
        m = fmaxf(m, zfin[o] + g_xt[o]);
    }
    float val = m * Wc[d * 4096 + hw];

    __shared__ float red[256];
    red[threadIdx.x] = val;
    __syncthreads();
    for (int off = 128; off > 0; off >>= 1) {
        if (threadIdx.x < off) red[threadIdx.x] += red[threadIdx.x + off];
        __syncthreads();
    }
    if (threadIdx.x == 0) atomicAdd(&g_logits[b], red[0]);
}

__global__ void final_kernel(const float* __restrict__ bc, float* __restrict__ out)
{
    int b = threadIdx.x;
    if (b < Bb) {
        float lg = g_logits[b] + bc[0];
        out[b] = 1.0f / (1.0f + __expf(-lg));
    }
}

// ---------------------------------------------------------------------------
extern "C" void kernel_launch(void* const* d_in, const int* in_sizes, int n_in,
                              void* d_out, int out_size)
{
    const float* x      = (const float*)d_in[0];
    const float* conv_w = (const float*)d_in[1];
    const float* pos_s  = (const float*)d_in[2];
    const float* pos_h  = (const float*)d_in[3];
    const float* pos_w  = (const float*)d_in[4];
    const float* Wq     = (const float*)d_in[5];
    const float* Wkv    = (const float*)d_in[6];
    const float* Wo     = (const float*)d_in[7];
    const float* bo     = (const float*)d_in[8];
    const float* Wc     = (const float*)d_in[9];
    const float* bc     = (const float*)d_in[10];
    float* out = (float*)d_out;

    float *pXt = nullptr, *pA = nullptr, *pB = nullptr;
    cudaGetSymbolAddress((void**)&pXt, g_xt);
    cudaGetSymbolAddress((void**)&pA,  g_bufA);
    cudaGetSymbolAddress((void**)&pB,  g_bufB);

    embed_kernel<<<(NPOS + 255) / 256, 256>>>(x, conv_w, pos_s, pos_h, pos_w);

    float* cur = pXt;
    for (int l = 0; l < NLl; l++) {
        float* nxt = (l & 1) ? pB : pA;
        const float* wq0 = Wq  + (l * 3 + 0) * 128;
        const float* wk0 = Wkv + (l * 3 + 0) * 256;
        const float* wo0 = Wo  + (l * 3 + 0) * 128;
        const float* bo0 = bo  + (l * 3 + 0) * 8;

        // axis 1 (S, L=20): write
        axial_attn20<2><<<Bb * IMm * IMm / 2, 256>>>(
            cur, nxt, wq0, wk0, wo0, bo0,
            IMm * IMm, Ss * IMm * IMm, IMm * IMm, 0);
        // axis 2 (H, L=64): accumulate
        axial_attn64<<<Bb * Ss * IMm, 128>>>(
            cur, nxt, wq0 + 128, wk0 + 256, wo0 + 128, bo0 + 8,
            IMm, IMm * IMm, IMm, 1);
        // axis 3 (W, L=64): accumulate
        axial_attn64<<<Bb * Ss * IMm, 128>>>(
            cur, nxt, wq0 + 256, wk0 + 512, wo0 + 256, bo0 + 16,
            1, IMm, 1, 1);
        cur = nxt;
    }

    {
        dim3 grid(IMm * IMm * Dd / 256, Bb);
        reduce_kernel<<<grid, 256>>>(cur, Wc);
    }
    final_kernel<<<1, 32>>>(bc, out);
}

// round 9
// speedup vs baseline: 1.4221x; 1.1519x over previous
#include <cuda_runtime.h>
#include <math.h>

// Problem constants
#define Bb 4
#define Ss 20
#define IMm 64
#define Dd 8
#define NLl 4
#define NPOS (Bb*Ss*IMm*IMm)
#define NELEM (NPOS*Dd)
#define LOG2E 1.4426950408889634f
#define QSCALE (0.5f * LOG2E)

// Scratch (no allocations allowed)
__device__ float g_xt[NELEM];
__device__ float g_bufA[NELEM];
__device__ float g_bufB[NELEM];
__device__ float g_logits[Bb];

// ---------------- packed f32x2 helpers (sm_103a) ----------------
typedef unsigned long long u64t;
__device__ __forceinline__ u64t pk2(float lo, float hi) {
    u64t r; asm("mov.b64 %0, {%1,%2};" : "=l"(r) : "f"(lo), "f"(hi)); return r;
}
__device__ __forceinline__ void up2(u64t v, float& a, float& b) {
    asm("mov.b64 {%0,%1}, %2;" : "=f"(a), "=f"(b) : "l"(v));
}
__device__ __forceinline__ u64t fma2(u64t a, u64t b, u64t c) {
    u64t d; asm("fma.rn.f32x2 %0, %1, %2, %3;" : "=l"(d) : "l"(a), "l"(b), "l"(c)); return d;
}
__device__ __forceinline__ u64t mul2(u64t a, u64t b) {
    u64t d; asm("mul.rn.f32x2 %0, %1, %2;" : "=l"(d) : "l"(a), "l"(b)); return d;
}
__device__ __forceinline__ u64t add2(u64t a, u64t b) {
    u64t d; asm("add.rn.f32x2 %0, %1, %2;" : "=l"(d) : "l"(a), "l"(b)); return d;
}
__device__ __forceinline__ float ex2f(float x) {
    float r; asm("ex2.approx.f32 %0, %1;" : "=f"(r) : "f"(x)); return r;
}

// ---------------------------------------------------------------------------
// Embed
// ---------------------------------------------------------------------------
__global__ void embed_kernel(const float* __restrict__ x,
                             const float* __restrict__ conv_w,
                             const float* __restrict__ pos_s,
                             const float* __restrict__ pos_h,
                             const float* __restrict__ pos_w)
{
    int idx = blockIdx.x * blockDim.x + threadIdx.x;
    if (idx < Bb) g_logits[idx] = 0.0f;
    if (idx >= NPOS) return;
    int w = idx & 63;
    int t = idx >> 6;
    int h = t & 63;
    t >>= 6;
    int s = t % Ss;
    float xv = x[idx];
    float vals[8];
#pragma unroll
    for (int d = 0; d < 8; d++) {
        float v = fmaxf(xv * conv_w[d], 0.0f);
        v += pos_s[s * 8 + d] + pos_h[d * 64 + h] + pos_w[d * 64 + w];
        vals[d] = v;
    }
    float4* o = (float4*)(g_xt + (long)idx * 8);
    o[0] = make_float4(vals[0], vals[1], vals[2], vals[3]);
    o[1] = make_float4(vals[4], vals[5], vals[6], vals[7]);
}

// ---------------------------------------------------------------------------
// Axial attention, L=64. 128 threads = 4 heads x 32 lanes. Each thread
// handles TWO rows (i, i+32) of its head -> K/V smem reads amortized 2x.
// Single-pass softmax in log2 domain (no max; args O(1), exp2 safe).
// ---------------------------------------------------------------------------
__global__ void __launch_bounds__(128, 6)
axial_attn64(const float* __restrict__ zin, float* __restrict__ zout,
             const float* __restrict__ Wq, const float* __restrict__ Wkv,
             const float* __restrict__ Wo, const float* __restrict__ bo,
             int inner_count, int outer_mult, int stride, int accum)
{
    __shared__ float  sWq[128];        // pre-scaled by 0.5*log2e
    __shared__ float2 sKV2[8][16];     // [d][h*4+e] = (k_w, v_w)
    __shared__ float  sWo[128];
    __shared__ float  sbo[8];
    __shared__ __align__(16) float sK[4][4][64];   // [h][e][j]
    __shared__ __align__(16) float sV[4][4][64];
    __shared__ float  sPart[4][8][64]; // [h][d][row]

    const int tid = threadIdx.x;      // 0..127
    const int h   = tid >> 5;         // head
    const int i0  = tid & 31;         // lane: rows i0 and i0+32

    sWq[tid] = Wq[tid] * QSCALE;
    {
        int d = tid >> 4, c = tid & 15;
        sKV2[d][c] = make_float2(Wkv[d * 32 + c], Wkv[d * 32 + 16 + c]);
    }
    sWo[tid] = Wo[tid];
    if (tid < 8) sbo[tid] = bo[tid];

    const int seq   = blockIdx.x;
    const int outer = seq / inner_count;
    const int rem   = seq - outer * inner_count;
    const long base = (long)outer * outer_mult + rem;

    // load my two rows
    const float* zrA = zin + (base + (long)i0 * stride) * 8;
    const float* zrB = zin + (base + (long)(i0 + 32) * stride) * 8;
    float4 aA0 = *(const float4*)zrA;
    float4 aA1 = *(const float4*)(zrA + 4);
    float4 aB0 = *(const float4*)zrB;
    float4 aB1 = *(const float4*)(zrB + 4);
    float rowA[8] = {aA0.x, aA0.y, aA0.z, aA0.w, aA1.x, aA1.y, aA1.z, aA1.w};
    float rowB[8] = {aB0.x, aB0.y, aB0.z, aB0.w, aB1.x, aB1.y, aB1.z, aB1.w};

    __syncthreads();  // weights ready

    // k,v projection (packed over (k,v)) for both rows -> shared
    const u64t* kvw = (const u64t*)&sKV2[0][0];
#pragma unroll
    for (int e = 0; e < 4; e++) {
        u64t wA = kvw[0 * 16 + h * 4 + e];
        u64t accA = mul2(pk2(rowA[0], rowA[0]), wA);
        u64t accB = mul2(pk2(rowB[0], rowB[0]), wA);
#pragma unroll
        for (int d = 1; d < 8; d++) {
            u64t w = kvw[d * 16 + h * 4 + e];
            accA = fma2(pk2(rowA[d], rowA[d]), w, accA);
            accB = fma2(pk2(rowB[d], rowB[d]), w, accB);
        }
        float kA, vA, kB, vB;
        up2(accA, kA, vA);
        up2(accB, kB, vB);
        sK[h][e][i0]      = kA;  sV[h][e][i0]      = vA;
        sK[h][e][i0 + 32] = kB;  sV[h][e][i0 + 32] = vB;
    }

    // q projection (pre-scaled) for both rows
    u64t qpA[4], qpB[4];
#pragma unroll
    for (int e = 0; e < 4; e++) {
        float sA = 0.0f, sB = 0.0f;
#pragma unroll
        for (int d = 0; d < 8; d++) {
            float w = sWq[d * 16 + h * 4 + e];
            sA = fmaf(rowA[d], w, sA);
            sB = fmaf(rowB[d], w, sB);
        }
        qpA[e] = pk2(sA, sA);
        qpB[e] = pk2(sB, sB);
    }
    __syncthreads();

    const ulonglong2* K0 = (const ulonglong2*)sK[h][0];
    const ulonglong2* K1 = (const ulonglong2*)sK[h][1];
    const ulonglong2* K2 = (const ulonglong2*)sK[h][2];
    const ulonglong2* K3 = (const ulonglong2*)sK[h][3];
    const ulonglong2* V0 = (const ulonglong2*)sV[h][0];
    const ulonglong2* V1 = (const ulonglong2*)sV[h][1];
    const ulonglong2* V2 = (const ulonglong2*)sV[h][2];
    const ulonglong2* V3 = (const ulonglong2*)sV[h][3];

    u64t zero = pk2(0.0f, 0.0f);
    u64t sAp = zero, sBp = zero;
    u64t oA0 = zero, oA1 = zero, oA2 = zero, oA3 = zero;
    u64t oB0 = zero, oB1 = zero, oB2 = zero, oB3 = zero;
#pragma unroll
    for (int jg = 0; jg < 16; jg++) {
        ulonglong2 k0 = K0[jg], k1 = K1[jg], k2 = K2[jg], k3 = K3[jg];
        // row A dots
        u64t dA01 = mul2(qpA[0], k0.x);
        dA01 = fma2(qpA[1], k1.x, dA01);
        dA01 = fma2(qpA[2], k2.x, dA01);
        dA01 = fma2(qpA[3], k3.x, dA01);
        u64t dA23 = mul2(qpA[0], k0.y);
        dA23 = fma2(qpA[1], k1.y, dA23);
        dA23 = fma2(qpA[2], k2.y, dA23);
        dA23 = fma2(qpA[3], k3.y, dA23);
        // row B dots
        u64t dB01 = mul2(qpB[0], k0.x);
        dB01 = fma2(qpB[1], k1.x, dB01);
        dB01 = fma2(qpB[2], k2.x, dB01);
        dB01 = fma2(qpB[3], k3.x, dB01);
        u64t dB23 = mul2(qpB[0], k0.y);
        dB23 = fma2(qpB[1], k1.y, dB23);
        dB23 = fma2(qpB[2], k2.y, dB23);
        dB23 = fma2(qpB[3], k3.y, dB23);
        float xa0, xa1, xa2, xa3, xb0, xb1, xb2, xb3;
        up2(dA01, xa0, xa1); up2(dA23, xa2, xa3);
        up2(dB01, xb0, xb1); up2(dB23, xb2, xb3);
        u64t eA01 = pk2(ex2f(xa0), ex2f(xa1));
        u64t eA23 = pk2(ex2f(xa2), ex2f(xa3));
        u64t eB01 = pk2(ex2f(xb0), ex2f(xb1));
        u64t eB23 = pk2(ex2f(xb2), ex2f(xb3));
        sAp = add2(add2(sAp, eA01), eA23);
        sBp = add2(add2(sBp, eB01), eB23);
        ulonglong2 v0 = V0[jg], v1 = V1[jg], v2 = V2[jg], v3 = V3[jg];
        oA0 = fma2(eA01, v0.x, oA0); oA0 = fma2(eA23, v0.y, oA0);
        oA1 = fma2(eA01, v1.x, oA1); oA1 = fma2(eA23, v1.y, oA1);
        oA2 = fma2(eA01, v2.x, oA2); oA2 = fma2(eA23, v2.y, oA2);
        oA3 = fma2(eA01, v3.x, oA3); oA3 = fma2(eA23, v3.y, oA3);
        oB0 = fma2(eB01, v0.x, oB0); oB0 = fma2(eB23, v0.y, oB0);
        oB1 = fma2(eB01, v1.x, oB1); oB1 = fma2(eB23, v1.y, oB1);
        oB2 = fma2(eB01, v2.x, oB2); oB2 = fma2(eB23, v2.y, oB2);
        oB3 = fma2(eB01, v3.x, oB3); oB3 = fma2(eB23, v3.y, oB3);
    }

    float ua, ub, oeA[4], oeB[4];
    up2(sAp, ua, ub);
    float invA = 1.0f / (ua + ub);
    up2(sBp, ua, ub);
    float invB = 1.0f / (ua + ub);
    up2(oA0, ua, ub); oeA[0] = (ua + ub) * invA;
    up2(oA1, ua, ub); oeA[1] = (ua + ub) * invA;
    up2(oA2, ua, ub); oeA[2] = (ua + ub) * invA;
    up2(oA3, ua, ub); oeA[3] = (ua + ub) * invA;
    up2(oB0, ua, ub); oeB[0] = (ua + ub) * invB;
    up2(oB1, ua, ub); oeB[1] = (ua + ub) * invB;
    up2(oB2, ua, ub); oeB[2] = (ua + ub) * invB;
    up2(oB3, ua, ub); oeB[3] = (ua + ub) * invB;

    // partial output projection for this head -> sPart
#pragma unroll
    for (int d = 0; d < 8; d++) {
        float w0 = sWo[(h * 4 + 0) * 8 + d];
        float w1 = sWo[(h * 4 + 1) * 8 + d];
        float w2 = sWo[(h * 4 + 2) * 8 + d];
        float w3 = sWo[(h * 4 + 3) * 8 + d];
        sPart[h][d][i0]      = oeA[0]*w0 + oeA[1]*w1 + oeA[2]*w2 + oeA[3]*w3;
        sPart[h][d][i0 + 32] = oeB[0]*w0 + oeB[1]*w1 + oeB[2]*w2 + oeB[3]*w3;
    }
    __syncthreads();

    // final: 128 threads, (row, dhalf) = (tid>>1, tid&1)
    {
        const int row = tid >> 1;
        const int dh  = (tid & 1) * 4;
        float o0 = sbo[dh+0], o1 = sbo[dh+1], o2 = sbo[dh+2], o3 = sbo[dh+3];
#pragma unroll
        for (int hh = 0; hh < 4; hh++) {
            o0 += sPart[hh][dh+0][row];
            o1 += sPart[hh][dh+1][row];
            o2 += sPart[hh][dh+2][row];
            o3 += sPart[hh][dh+3][row];
        }
        float* zo = zout + (base + (long)row * stride) * 8 + dh;
        if (accum) {
            float4 prev = *(float4*)zo;
            o0 += prev.x; o1 += prev.y; o2 += prev.z; o3 += prev.w;
        }
        *(float4*)zo = make_float4(o0, o1, o2, o3);
    }
}

// ---------------------------------------------------------------------------
// Axial attention, L=20 (sequence axis). One thread per row (all 4 heads).
// Fewer, fatter blocks: 2048 blocks x 160 threads.
// ---------------------------------------------------------------------------
template<int L, int NS>
__global__ void __launch_bounds__(L*NS)
axial_attn20(const float* __restrict__ zin, float* __restrict__ zout,
             const float* __restrict__ Wq, const float* __restrict__ Wkv,
             const float* __restrict__ Wo, const float* __restrict__ bo,
             int inner_count, int outer_mult, int stride, int accum)
{
    __shared__ float sWq[128];     // pre-scaled
    __shared__ float sWkv[256];
    __shared__ float sWo[128];
    __shared__ float sbo[8];
    __shared__ float4 sKq[NS][4][L];
    __shared__ float4 sVq[NS][4][L];

    const int i   = threadIdx.x;
    const int sl  = threadIdx.y;
    const int tid = sl * L + i;
    const int nth = L * NS;

    for (int t = tid; t < 128; t += nth) sWq[t]  = Wq[t] * QSCALE;
    for (int t = tid; t < 256; t += nth) sWkv[t] = Wkv[t];
    for (int t = tid; t < 128; t += nth) sWo[t]  = Wo[t];
    if (tid < 8) sbo[tid] = bo[tid];

    const int seq   = blockIdx.x * NS + sl;
    const int outer = seq / inner_count;
    const int rem   = seq - outer * inner_count;
    const long base = (long)outer * outer_mult + rem;

    const float* zr = zin + (base + (long)i * stride) * 8;
    float4 a0 = *(const float4*)zr;
    float4 a1 = *(const float4*)(zr + 4);
    float row[8] = {a0.x, a0.y, a0.z, a0.w, a1.x, a1.y, a1.z, a1.w};

    __syncthreads();

    float q[16];
#pragma unroll
    for (int c = 0; c < 16; c++) {
        float s = 0.0f;
#pragma unroll
        for (int d = 0; d < 8; d++) s = fmaf(row[d], sWq[d * 16 + c], s);
        q[c] = s;
    }
#pragma unroll
    for (int h = 0; h < 4; h++) {
        float4 kk, vv;
        float* kp = (float*)&kk;
        float* vp = (float*)&vv;
#pragma unroll
        for (int e = 0; e < 4; e++) {
            float sk = 0.0f, sv = 0.0f;
#pragma unroll
            for (int d = 0; d < 8; d++) {
                sk = fmaf(row[d], sWkv[d * 32 + h * 4 + e], sk);
                sv = fmaf(row[d], sWkv[d * 32 + 16 + h * 4 + e], sv);
            }
            kp[e] = sk; vp[e] = sv;
        }
        sKq[sl][h][i] = kk;
        sVq[sl][h][i] = vv;
    }
    __syncthreads();

    float oacc[16];
#pragma unroll
    for (int h = 0; h < 4; h++) {
        const float qx = q[h*4+0], qy = q[h*4+1], qz = q[h*4+2], qw = q[h*4+3];
        float ssum = 0.0f;
        float ox = 0.f, oy = 0.f, oz = 0.f, ow = 0.f;
#pragma unroll
        for (int j = 0; j < L; j++) {
            float4 kj = sKq[sl][h][j];
            float d = qx*kj.x + qy*kj.y + qz*kj.z + qw*kj.w;
            float e = ex2f(d);
            ssum += e;
            float4 vj = sVq[sl][h][j];
            ox = fmaf(e, vj.x, ox);
            oy = fmaf(e, vj.y, oy);
            oz = fmaf(e, vj.z, oz);
            ow = fmaf(e, vj.w, ow);
        }
        float inv = 1.0f / ssum;
        oacc[h*4+0] = ox * inv;
        oacc[h*4+1] = oy * inv;
        oacc[h*4+2] = oz * inv;
        oacc[h*4+3] = ow * inv;
    }

    float outv[8];
#pragma unroll
    for (int d = 0; d < 8; d++) {
        float s = sbo[d];
#pragma unroll
        for (int c = 0; c < 16; c++) s = fmaf(oacc[c], sWo[c * 8 + d], s);
        outv[d] = s;
    }

    float* zo = zout + (base + (long)i * stride) * 8;
    if (accum) {
        float4 o0 = *(float4*)zo;
        float4 o1 = *(float4*)(zo + 4);
        outv[0] += o0.x; outv[1] += o0.y; outv[2] += o0.z; outv[3] += o0.w;
        outv[4] += o1.x; outv[5] += o1.y; outv[6] += o1.z; outv[7] += o1.w;
    }
    ((float4*)zo)[0] = make_float4(outv[0], outv[1], outv[2], outv[3]);
    ((float4*)zo)[1] = make_float4(outv[4], outv[5], outv[6], outv[7]);
}

// ---------------------------------------------------------------------------
// Epilogue
// ---------------------------------------------------------------------------
__global__ void reduce_kernel(const float* __restrict__ zfin,
                              const float* __restrict__ Wc)
{
    const int b = blockIdx.y;
    const int t = blockIdx.x * blockDim.x + threadIdx.x;
    const int d  = t & 7;
    const int hw = t >> 3;
    long base = (long)b * Ss * 32768 + (long)hw * 8 + d;
    float m = -1e30f;
#pragma unroll
    for (int s = 0; s < Ss; s++) {
        long o = base + (long)s * 32768;
        m = fmaxf(m, zfin[o] + g_xt[o]);
    }
    float val = m * Wc[d * 4096 + hw];

    __shared__ float red[256];
    red[threadIdx.x] = val;
    __syncthreads();
    for (int off = 128; off > 0; off >>= 1) {
        if (threadIdx.x < off) red[threadIdx.x] += red[threadIdx.x + off];
        __syncthreads();
    }
    if (threadIdx.x == 0) atomicAdd(&g_logits[b], red[0]);
}

__global__ void final_kernel(const float* __restrict__ bc, float* __restrict__ out)
{
    int b = threadIdx.x;
    if (b < Bb) {
        float lg = g_logits[b] + bc[0];
        out[b] = 1.0f / (1.0f + __expf(-lg));
    }
}

// ---------------------------------------------------------------------------
extern "C" void kernel_launch(void* const* d_in, const int* in_sizes, int n_in,
                              void* d_out, int out_size)
{
    const float* x      = (const float*)d_in[0];
    const float* conv_w = (const float*)d_in[1];
    const float* pos_s  = (const float*)d_in[2];
    const float* pos_h  = (const float*)d_in[3];
    const float* pos_w  = (const float*)d_in[4];
    const float* Wq     = (const float*)d_in[5];
    const float* Wkv    = (const float*)d_in[6];
    const float* Wo     = (const float*)d_in[7];
    const float* bo     = (const float*)d_in[8];
    const float* Wc     = (const float*)d_in[9];
    const float* bc     = (const float*)d_in[10];
    float* out = (float*)d_out;

    float *pXt = nullptr, *pA = nullptr, *pB = nullptr;
    cudaGetSymbolAddress((void**)&pXt, g_xt);
    cudaGetSymbolAddress((void**)&pA,  g_bufA);
    cudaGetSymbolAddress((void**)&pB,  g_bufB);

    embed_kernel<<<(NPOS + 255) / 256, 256>>>(x, conv_w, pos_s, pos_h, pos_w);

    float* cur = pXt;
    for (int l = 0; l < NLl; l++) {
        float* nxt = (l & 1) ? pB : pA;
        const float* wq0 = Wq  + (l * 3 + 0) * 128;
        const float* wk0 = Wkv + (l * 3 + 0) * 256;
        const float* wo0 = Wo  + (l * 3 + 0) * 128;
        const float* bo0 = bo  + (l * 3 + 0) * 8;

        // axis 1 (S, L=20): write
        {
            dim3 blk(20, 8);
            axial_attn20<20, 8><<<Bb * IMm * IMm / 8, blk>>>(
                cur, nxt, wq0, wk0, wo0, bo0,
                IMm * IMm, Ss * IMm * IMm, IMm * IMm, 0);
        }
        // axis 2 (H, L=64): accumulate
        axial_attn64<<<Bb * Ss * IMm, 128>>>(
            cur, nxt, wq0 + 128, wk0 + 256, wo0 + 128, bo0 + 8,
            IMm, IMm * IMm, IMm, 1);
        // axis 3 (W, L=64): accumulate
        axial_attn64<<<Bb * Ss * IMm, 128>>>(
            cur, nxt, wq0 + 256, wk0 + 512, wo0 + 256, bo0 + 16,
            1, IMm, 1, 1);
        cur = nxt;
    }

    {
        dim3 grid(IMm * IMm * Dd / 256, Bb);
        reduce_kernel<<<grid, 256>>>(cur, Wc);
    }
    final_kernel<<<1, 32>>>(bc, out);
}